// round 2
// baseline (speedup 1.0000x reference)
#include <cuda_runtime.h>
#include <cstdint>

// Problem dims: S=128, I=J=512, CM=256, C=D=32, CZ=128
#define NROWS   65536          // S*I
#define ABLD    16384          // 512*32, row stride of g_A/g_B per s
#define OS_STR  1028           // padded o_s row stride (floats)
#define WO_ROW  68             // padded Wo_s row stride (floats)
#define WO_BUF  (128*WO_ROW)   // 8704 floats per Wo chunk buffer
#define AS_OFF  0
#define BS_OFF  16384
#define OS_OFF  0              // overlaps AS (used after phase-A sync)
#define WO_OFF  32768
#define K2_SMEM ((32768 + 2*WO_BUF) * 4)   // 200704 bytes
#define K1_SMEM ((2*32*260 + 8*256) * 4)   // 74752 bytes

// Scratch (8 MB each): a[s][i][c], b[s][j][d], layout [s*16384 + i*32 + c]
__device__ float g_A[128 * 512 * 32];
__device__ float g_B[128 * 512 * 32];

__device__ __forceinline__ void cp16(void* dst, const void* src) {
    unsigned d = (unsigned)__cvta_generic_to_shared(dst);
    asm volatile("cp.async.cg.shared.global [%0], [%1], 16;" :: "r"(d), "l"(src));
}
__device__ __forceinline__ void cp_commit() { asm volatile("cp.async.commit_group;"); }
template<int N> __device__ __forceinline__ void cp_wait() {
    asm volatile("cp.async.wait_group %0;" :: "n"(N));
}

// =====================================================================
// Kernel 1: LayerNorm + dual projection (a = ln@Wa^T, b = ln@Wb^T).
// 256 threads = 8 warps; warp w owns row (s,i) = blockIdx.x*8 + w.
// =====================================================================
__global__ __launch_bounds__(256, 2)
void ln_proj_kernel(const float* __restrict__ x,
                    const float* __restrict__ nw,
                    const float* __restrict__ nb,
                    const float* __restrict__ Wa,
                    const float* __restrict__ Wb)
{
    extern __shared__ float sm[];
    float* Wa_s = sm;              // [32][260] padded
    float* Wb_s = sm + 32 * 260;   // [32][260]
    float* ln_s = sm + 2 * 32 * 260; // [8][256]

    const int t    = threadIdx.x;
    const int lane = t & 31;
    const int w    = t >> 5;

    // Stage Wa/Wb (each [32][256]) with pad-260 rows: bank = (4c+m)%32.
    for (int idx = t; idx < 8192; idx += 256) {
        int c = idx >> 8, m = idx & 255;
        Wa_s[c * 260 + m] = Wa[idx];
        Wb_s[c * 260 + m] = Wb[idx];
    }

    const int row = blockIdx.x * 8 + w;
    const float* xr = x + (size_t)row * 256;

    // LayerNorm of this warp's row: 8 elems/lane.
    float v[8];
    float s = 0.f, sq = 0.f;
    #pragma unroll
    for (int h = 0; h < 2; h++) {
        float4 x4 = *(const float4*)(xr + lane * 4 + 128 * h);
        v[h*4+0] = x4.x; v[h*4+1] = x4.y; v[h*4+2] = x4.z; v[h*4+3] = x4.w;
        s  += x4.x + x4.y + x4.z + x4.w;
        sq += x4.x*x4.x + x4.y*x4.y + x4.z*x4.z + x4.w*x4.w;
    }
    #pragma unroll
    for (int o = 16; o > 0; o >>= 1) {
        s  += __shfl_xor_sync(0xffffffffu, s,  o);
        sq += __shfl_xor_sync(0xffffffffu, sq, o);
    }
    float mu  = s * (1.f / 256.f);
    float var = sq * (1.f / 256.f) - mu * mu;
    float rs  = rsqrtf(var + 1e-5f);
    #pragma unroll
    for (int h = 0; h < 2; h++) {
        int m0 = lane * 4 + 128 * h;
        float4 w4 = *(const float4*)(nw + m0);
        float4 b4 = *(const float4*)(nb + m0);
        float* lp = ln_s + w * 256 + m0;
        lp[0] = (v[h*4+0] - mu) * rs * w4.x + b4.x;
        lp[1] = (v[h*4+1] - mu) * rs * w4.y + b4.y;
        lp[2] = (v[h*4+2] - mu) * rs * w4.z + b4.z;
        lp[3] = (v[h*4+3] - mu) * rs * w4.w + b4.w;
    }
    __syncthreads();   // Wa_s/Wb_s staged + ln_s visible

    // Projection: lane computes a[row][lane], b[row][lane] over 256 m.
    float accA = 0.f, accB = 0.f;
    const float* lr  = ln_s + w * 256;
    const float* war = Wa_s + lane * 260;
    const float* wbr = Wb_s + lane * 260;
    #pragma unroll 8
    for (int m4 = 0; m4 < 64; m4++) {
        float4 l4  = *(const float4*)(lr  + m4 * 4);   // warp broadcast
        float4 wa4 = *(const float4*)(war + m4 * 4);
        float4 wb4 = *(const float4*)(wbr + m4 * 4);
        accA = fmaf(l4.x, wa4.x, accA); accA = fmaf(l4.y, wa4.y, accA);
        accA = fmaf(l4.z, wa4.z, accA); accA = fmaf(l4.w, wa4.w, accA);
        accB = fmaf(l4.x, wb4.x, accB); accB = fmaf(l4.y, wb4.y, accB);
        accB = fmaf(l4.z, wb4.z, accB); accB = fmaf(l4.w, wb4.w, accB);
    }
    g_A[row * 32 + lane] = accA;
    g_B[row * 32 + lane] = accB;
}

// =====================================================================
// Kernel 2: fused outer-product-mean + output projection.
// Grid (128,128): CTA = 4x4 (i,j) pairs.
// Phase A: O[128x128] = sum_s A[s][128ic] B[s][128jd]  (register GEMM, K=128)
// Phase B: per pair z[128] = Wo[128x1024] . o_vec; Wo streamed via cp.async
//          double buffer, 16 chunks of 64 k.
// =====================================================================
__global__ __launch_bounds__(256, 1)
void opm_kernel(const float* __restrict__ Wo,
                const float* __restrict__ bo,
                float* __restrict__ out)
{
    extern __shared__ float sm[];
    const int t  = threadIdx.x;
    const int bx = blockIdx.x;   // j tile
    const int by = blockIdx.y;   // i tile

    // ---- stage A/B tiles + prefetch Wo chunks 0,1 ----
    {
        const float* Ab = g_A + by * 128;
        const float* Bb = g_B + bx * 128;
        #pragma unroll
        for (int q = 0; q < 16; q++) {
            int idx = t + 256 * q;
            int r = idx >> 5, c4 = (idx & 31) * 4;
            cp16(&sm[AS_OFF + r * 128 + c4], Ab + (size_t)r * ABLD + c4);
        }
        #pragma unroll
        for (int q = 0; q < 16; q++) {
            int idx = t + 256 * q;
            int r = idx >> 5, c4 = (idx & 31) * 4;
            cp16(&sm[BS_OFF + r * 128 + c4], Bb + (size_t)r * ABLD + c4);
        }
        cp_commit();                               // group: A/B
        #pragma unroll
        for (int ck = 0; ck < 2; ck++) {
            #pragma unroll
            for (int q = 0; q < 8; q++) {
                int idx = t + 256 * q;
                int r = idx >> 4, j4 = (idx & 15) * 4;
                cp16(&sm[WO_OFF + ck * WO_BUF + r * WO_ROW + j4],
                     Wo + r * 1024 + ck * 64 + j4);
            }
            cp_commit();                           // groups: chunk0, chunk1
        }
    }
    cp_wait<2>();     // A/B tiles landed (chunks 0,1 may still fly)
    __syncthreads();

    // ---- Phase A ----
    const int tx = t & 15, ty = t >> 4;
    float acc[8][8];
    #pragma unroll
    for (int u = 0; u < 8; u++)
        #pragma unroll
        for (int v = 0; v < 8; v++) acc[u][v] = 0.f;

    #pragma unroll 2
    for (int s = 0; s < 128; s++) {
        float a8[8], b8[8];
        float4 f;
        f = *(const float4*)&sm[AS_OFF + s * 128 + ty * 8];
        a8[0]=f.x; a8[1]=f.y; a8[2]=f.z; a8[3]=f.w;
        f = *(const float4*)&sm[AS_OFF + s * 128 + ty * 8 + 4];
        a8[4]=f.x; a8[5]=f.y; a8[6]=f.z; a8[7]=f.w;
        f = *(const float4*)&sm[BS_OFF + s * 128 + tx * 8];
        b8[0]=f.x; b8[1]=f.y; b8[2]=f.z; b8[3]=f.w;
        f = *(const float4*)&sm[BS_OFF + s * 128 + tx * 8 + 4];
        b8[4]=f.x; b8[5]=f.y; b8[6]=f.z; b8[7]=f.w;
        #pragma unroll
        for (int u = 0; u < 8; u++)
            #pragma unroll
            for (int v = 0; v < 8; v++)
                acc[u][v] = fmaf(a8[u], b8[v], acc[u][v]);
    }
    __syncthreads();   // done reading A_s/B_s; o_s may overwrite

    // ---- O -> o_s[pair][c*32+d], scaled by 1/S ----
    {
        const int pr    = (ty >> 2) * 4 + (tx >> 2);
        const int cbase = (ty & 3) * 8;
        const int dbase = (tx & 3) * 8;
        #pragma unroll
        for (int u = 0; u < 8; u++) {
            #pragma unroll
            for (int v = 0; v < 8; v += 4) {
                float4 w4;
                w4.x = acc[u][v+0] * (1.f / 128.f);
                w4.y = acc[u][v+1] * (1.f / 128.f);
                w4.z = acc[u][v+2] * (1.f / 128.f);
                w4.w = acc[u][v+3] * (1.f / 128.f);
                *(float4*)&sm[OS_OFF + pr * OS_STR + (cbase + u) * 32 + dbase + v] = w4;
            }
        }
    }
    __syncthreads();

    // ---- Phase B: thread = (cz, ph); 8 pairs x 1 cz each ----
    const int cz = t & 127;
    const int ph = t >> 7;
    float z[8];
    #pragma unroll
    for (int p = 0; p < 8; p++) z[p] = 0.f;

    for (int kc = 0; kc < 16; kc++) {
        cp_wait<1>();          // chunk kc landed (positional: all but newest group)
        __syncthreads();
        const float* wrow = &sm[WO_OFF + (kc & 1) * WO_BUF + cz * WO_ROW];
        const float* obase = &sm[OS_OFF + ph * 8 * OS_STR + kc * 64];
        #pragma unroll 4
        for (int kk = 0; kk < 16; kk++) {
            float4 w4 = *(const float4*)(wrow + kk * 4);
            #pragma unroll
            for (int p = 0; p < 8; p++) {
                float4 o4 = *(const float4*)(obase + p * OS_STR + kk * 4); // warp broadcast
                z[p] = fmaf(w4.x, o4.x, z[p]);
                z[p] = fmaf(w4.y, o4.y, z[p]);
                z[p] = fmaf(w4.z, o4.z, z[p]);
                z[p] = fmaf(w4.w, o4.w, z[p]);
            }
        }
        __syncthreads();       // everyone done with this buffer before refill
        if (kc + 2 < 16) {
            const int ck = kc + 2;
            #pragma unroll
            for (int q = 0; q < 8; q++) {
                int idx = t + 256 * q;
                int r = idx >> 4, j4 = (idx & 15) * 4;
                cp16(&sm[WO_OFF + (kc & 1) * WO_BUF + r * WO_ROW + j4],
                     Wo + r * 1024 + ck * 64 + j4);
            }
        }
        cp_commit();           // commit every iter (maybe empty) -> uniform wait<1>
    }

    // ---- writeout: z + bo ----
    {
        const float bov = bo[cz];
        #pragma unroll
        for (int p = 0; p < 8; p++) {
            int pr  = ph * 8 + p;
            int ipl = pr >> 2, jpl = pr & 3;
            int oidx = ((by * 4 + ipl) * 512 + bx * 4 + jpl) * 128 + cz;
            out[oidx] = z[p] + bov;
        }
    }
}

extern "C" void kernel_launch(void* const* d_in, const int* in_sizes, int n_in,
                              void* d_out, int out_size) {
    const float* x  = (const float*)d_in[0];
    const float* nw = (const float*)d_in[1];
    const float* nb = (const float*)d_in[2];
    const float* Wa = (const float*)d_in[3];
    const float* Wb = (const float*)d_in[4];
    const float* Wo = (const float*)d_in[5];
    const float* bo = (const float*)d_in[6];
    float* out = (float*)d_out;

    cudaFuncSetAttribute(ln_proj_kernel, cudaFuncAttributeMaxDynamicSharedMemorySize, K1_SMEM);
    cudaFuncSetAttribute(opm_kernel,     cudaFuncAttributeMaxDynamicSharedMemorySize, K2_SMEM);

    ln_proj_kernel<<<NROWS / 8, 256, K1_SMEM>>>(x, nw, nb, Wa, Wb);
    dim3 grid(128, 128);
    opm_kernel<<<grid, 256, K2_SMEM>>>(Wo, bo, out);
}

// round 4
// speedup vs baseline: 1.1083x; 1.1083x over previous
#include <cuda_runtime.h>
#include <cstdint>

// Problem dims: S=128, I=J=512, CM=256, C=D=32, CZ=128
#define NROWS   65536
#define ABLD    16384          // 512*32, row stride of g_A/g_B per s
#define AS_OFF  0              // A half tile: [64][128] floats
#define BS_OFF  8192           // B half tile: [64][128] floats
#define OS_STR  1028           // padded o_s row stride (floats), ≡4 mod 8
#define OS_OFF  0              // O overlaps A/B region (sequential use)
#define O_SIZE  (16*OS_STR)    // 16448 floats
#define WO_ROW  36             // 32 k + 4 pad
#define WO_BUF  (128*WO_ROW)   // 4608 floats per chunk buffer
#define WO_OFF  16448
#define N_CHUNK 32
#define K2_SMEM ((16448 + 2*WO_BUF) * 4)   // 102656 bytes
#define K1_SMEM ((2*32*260 + 8*256) * 4)   // 74752 bytes

typedef unsigned long long ull;

// Scratch (8 MB each): a[s][i][c], b[s][j][d], layout [s*16384 + i*32 + c]
__device__ float g_A[128 * 512 * 32];
__device__ float g_B[128 * 512 * 32];

__device__ __forceinline__ void cp16(void* dst, const void* src) {
    unsigned d = (unsigned)__cvta_generic_to_shared(dst);
    asm volatile("cp.async.cg.shared.global [%0], [%1], 16;" :: "r"(d), "l"(src));
}
__device__ __forceinline__ void cp_commit() { asm volatile("cp.async.commit_group;"); }
template<int N> __device__ __forceinline__ void cp_wait() {
    asm volatile("cp.async.wait_group %0;" :: "n"(N));
}
__device__ __forceinline__ ull pack2(float lo, float hi) {
    ull r; asm("mov.b64 %0, {%1,%2};" : "=l"(r) : "f"(lo), "f"(hi)); return r;
}
__device__ __forceinline__ void ffma2(ull& d, ull a, ull b) {
    asm("fma.rn.f32x2 %0, %1, %2, %0;" : "+l"(d) : "l"(a), "l"(b));
}
__device__ __forceinline__ float2 unpack2(ull v) {
    float2 f; asm("mov.b64 {%0,%1}, %2;" : "=f"(f.x), "=f"(f.y) : "l"(v)); return f;
}

// =====================================================================
// Kernel 1: LayerNorm + dual projection (a = ln@Wa^T, b = ln@Wb^T).
// =====================================================================
__global__ __launch_bounds__(256, 2)
void ln_proj_kernel(const float* __restrict__ x,
                    const float* __restrict__ nw,
                    const float* __restrict__ nb,
                    const float* __restrict__ Wa,
                    const float* __restrict__ Wb)
{
    extern __shared__ float sm[];
    float* Wa_s = sm;                 // [32][260]
    float* Wb_s = sm + 32 * 260;      // [32][260]
    float* ln_s = sm + 2 * 32 * 260;  // [8][256]

    const int t = threadIdx.x, lane = t & 31, w = t >> 5;

    for (int idx = t; idx < 8192; idx += 256) {
        int c = idx >> 8, m = idx & 255;
        Wa_s[c * 260 + m] = Wa[idx];
        Wb_s[c * 260 + m] = Wb[idx];
    }

    const int row = blockIdx.x * 8 + w;
    const float* xr = x + (size_t)row * 256;

    float v[8]; float s = 0.f, sq = 0.f;
    #pragma unroll
    for (int h = 0; h < 2; h++) {
        float4 x4 = *(const float4*)(xr + lane * 4 + 128 * h);
        v[h*4+0]=x4.x; v[h*4+1]=x4.y; v[h*4+2]=x4.z; v[h*4+3]=x4.w;
        s  += x4.x + x4.y + x4.z + x4.w;
        sq += x4.x*x4.x + x4.y*x4.y + x4.z*x4.z + x4.w*x4.w;
    }
    #pragma unroll
    for (int o = 16; o > 0; o >>= 1) {
        s  += __shfl_xor_sync(0xffffffffu, s,  o);
        sq += __shfl_xor_sync(0xffffffffu, sq, o);
    }
    float mu  = s * (1.f / 256.f);
    float var = sq * (1.f / 256.f) - mu * mu;
    float rs  = rsqrtf(var + 1e-5f);
    #pragma unroll
    for (int h = 0; h < 2; h++) {
        int m0 = lane * 4 + 128 * h;
        float4 w4 = *(const float4*)(nw + m0);
        float4 b4 = *(const float4*)(nb + m0);
        float* lp = ln_s + w * 256 + m0;
        lp[0] = (v[h*4+0]-mu)*rs*w4.x + b4.x;
        lp[1] = (v[h*4+1]-mu)*rs*w4.y + b4.y;
        lp[2] = (v[h*4+2]-mu)*rs*w4.z + b4.z;
        lp[3] = (v[h*4+3]-mu)*rs*w4.w + b4.w;
    }
    __syncthreads();

    float accA = 0.f, accB = 0.f;
    const float* lr  = ln_s + w * 256;
    const float* war = Wa_s + lane * 260;
    const float* wbr = Wb_s + lane * 260;
    #pragma unroll 8
    for (int m4 = 0; m4 < 64; m4++) {
        float4 l4  = *(const float4*)(lr  + m4 * 4);
        float4 wa4 = *(const float4*)(war + m4 * 4);
        float4 wb4 = *(const float4*)(wbr + m4 * 4);
        accA = fmaf(l4.x, wa4.x, accA); accA = fmaf(l4.y, wa4.y, accA);
        accA = fmaf(l4.z, wa4.z, accA); accA = fmaf(l4.w, wa4.w, accA);
        accB = fmaf(l4.x, wb4.x, accB); accB = fmaf(l4.y, wb4.y, accB);
        accB = fmaf(l4.z, wb4.z, accB); accB = fmaf(l4.w, wb4.w, accB);
    }
    g_A[row * 32 + lane] = accA;
    g_B[row * 32 + lane] = accB;
}

// =====================================================================
// Kernel 2: fused OPM + projection, f32x2 packed, 2 CTAs/SM.
// Phase A: K split in two s=64 passes; acc2[8][4] packed over d-pairs.
// Phase B: z packed over k; thread = (cz2 0..63, ph 0..3) owns
//          cz ∈ {cz2, cz2+64} × pairs {ph, 4+ph, 8+ph, 12+ph}.
// =====================================================================
__global__ __launch_bounds__(256, 2)
void opm_kernel(const float* __restrict__ Wo,
                const float* __restrict__ bo,
                float* __restrict__ out)
{
    extern __shared__ float sm[];
    const int t  = threadIdx.x;
    const int bx = blockIdx.x;   // j tile
    const int by = blockIdx.y;   // i tile

    // ---- prefetch: A/B pass-0 halves, then Wo chunks 0,1 ----
    {
        const float* Ab = g_A + by * 128;
        const float* Bb = g_B + bx * 128;
        #pragma unroll
        for (int q = 0; q < 8; q++) {
            int idx = t + 256 * q;
            int r = idx >> 5, c4 = (idx & 31) * 4;
            cp16(&sm[AS_OFF + r * 128 + c4], Ab + (size_t)r * ABLD + c4);
            cp16(&sm[BS_OFF + r * 128 + c4], Bb + (size_t)r * ABLD + c4);
        }
        cp_commit();                                  // G: AB pass 0
        #pragma unroll
        for (int ck = 0; ck < 2; ck++) {
            #pragma unroll
            for (int q = 0; q < 4; q++) {
                int idx = t + 256 * q;
                int r = idx >> 3, j4 = (idx & 7) * 4;
                cp16(&sm[WO_OFF + ck * WO_BUF + r * WO_ROW + j4],
                     Wo + r * 1024 + ck * 32 + j4);
            }
            cp_commit();                              // G: chunk ck
        }
    }

    // ---- Phase A ----
    const int tx = t & 15, ty = t >> 4;
    ull acc2[8][4];
    #pragma unroll
    for (int u = 0; u < 8; u++)
        #pragma unroll
        for (int vp = 0; vp < 4; vp++) acc2[u][vp] = 0ull;

    #pragma unroll 1
    for (int pass = 0; pass < 2; pass++) {
        if (pass == 0) cp_wait<2>();   // AB0 landed (Wo chunks may fly)
        else           cp_wait<0>();   // AB1 landed (everything in)
        __syncthreads();

        #pragma unroll 2
        for (int s = 0; s < 64; s++) {
            float4 fa0 = *(const float4*)&sm[AS_OFF + s * 128 + ty * 8];
            float4 fa1 = *(const float4*)&sm[AS_OFF + s * 128 + ty * 8 + 4];
            ull a2[8];
            a2[0]=pack2(fa0.x,fa0.x); a2[1]=pack2(fa0.y,fa0.y);
            a2[2]=pack2(fa0.z,fa0.z); a2[3]=pack2(fa0.w,fa0.w);
            a2[4]=pack2(fa1.x,fa1.x); a2[5]=pack2(fa1.y,fa1.y);
            a2[6]=pack2(fa1.z,fa1.z); a2[7]=pack2(fa1.w,fa1.w);
            ulonglong2 b0 = *(const ulonglong2*)&sm[BS_OFF + s * 128 + tx * 8];
            ulonglong2 b1 = *(const ulonglong2*)&sm[BS_OFF + s * 128 + tx * 8 + 4];
            ull bv[4] = {b0.x, b0.y, b1.x, b1.y};
            #pragma unroll
            for (int u = 0; u < 8; u++)
                #pragma unroll
                for (int vp = 0; vp < 4; vp++)
                    ffma2(acc2[u][vp], a2[u], bv[vp]);
        }
        __syncthreads();   // all warps done reading this half

        if (pass == 0) {   // stage second half
            const float* Ab = g_A + (size_t)64 * ABLD + by * 128;
            const float* Bb = g_B + (size_t)64 * ABLD + bx * 128;
            #pragma unroll
            for (int q = 0; q < 8; q++) {
                int idx = t + 256 * q;
                int r = idx >> 5, c4 = (idx & 31) * 4;
                cp16(&sm[AS_OFF + r * 128 + c4], Ab + (size_t)r * ABLD + c4);
                cp16(&sm[BS_OFF + r * 128 + c4], Bb + (size_t)r * ABLD + c4);
            }
            cp_commit();
        }
    }

    // ---- O -> o_s[pr][c*32+d] * (1/S) ----
    {
        const int pr    = (ty >> 2) * 4 + (tx >> 2);
        const int cbase = (ty & 3) * 8;
        const int dbase = (tx & 3) * 8;
        #pragma unroll
        for (int u = 0; u < 8; u++) {
            #pragma unroll
            for (int h = 0; h < 2; h++) {
                float2 p0 = unpack2(acc2[u][2*h+0]);
                float2 p1 = unpack2(acc2[u][2*h+1]);
                float4 w4;
                w4.x = p0.x * (1.f/128.f); w4.y = p0.y * (1.f/128.f);
                w4.z = p1.x * (1.f/128.f); w4.w = p1.y * (1.f/128.f);
                *(float4*)&sm[OS_OFF + pr * OS_STR + (cbase+u) * 32 + dbase + 4*h] = w4;
            }
        }
    }
    __syncthreads();

    // ---- Phase B ----
    const int cz2 = t >> 2;      // 0..63
    const int ph  = t & 3;       // 0..3
    ull zp[2][4];
    #pragma unroll
    for (int c = 0; c < 2; c++)
        #pragma unroll
        for (int j = 0; j < 4; j++) zp[c][j] = 0ull;

    for (int kc = 0; kc < N_CHUNK; kc++) {
        cp_wait<1>();
        __syncthreads();
        const float* wA = &sm[WO_OFF + (kc & 1) * WO_BUF + cz2 * WO_ROW];
        const float* wB = wA + 64 * WO_ROW;
        const float* ob = &sm[OS_OFF + ph * OS_STR + kc * 32];
        #pragma unroll
        for (int kk = 0; kk < 8; kk++) {
            ulonglong2 wa = *(const ulonglong2*)(wA + kk * 4);
            ulonglong2 wb = *(const ulonglong2*)(wB + kk * 4);
            #pragma unroll
            for (int j = 0; j < 4; j++) {
                ulonglong2 o = *(const ulonglong2*)(ob + j * 4 * OS_STR + kk * 4);
                ffma2(zp[0][j], wa.x, o.x);
                ffma2(zp[0][j], wa.y, o.y);
                ffma2(zp[1][j], wb.x, o.x);
                ffma2(zp[1][j], wb.y, o.y);
            }
        }
        __syncthreads();   // done with this buffer before refill
        if (kc + 2 < N_CHUNK) {
            const int ck = kc + 2;
            #pragma unroll
            for (int q = 0; q < 4; q++) {
                int idx = t + 256 * q;
                int r = idx >> 3, j4 = (idx & 7) * 4;
                cp16(&sm[WO_OFF + (kc & 1) * WO_BUF + r * WO_ROW + j4],
                     Wo + r * 1024 + ck * 32 + j4);
            }
        }
        cp_commit();       // uniform group count (maybe empty)
    }

    // ---- writeout: pairs pr = j*4+ph -> (i_local=j, j_local=ph) ----
    {
        const float boA = bo[cz2], boB = bo[cz2 + 64];
        #pragma unroll
        for (int j = 0; j < 4; j++) {
            int base = ((by * 4 + j) * 512 + bx * 4 + ph) * 128;
            float2 fa = unpack2(zp[0][j]);
            float2 fb = unpack2(zp[1][j]);
            out[base + cz2]      = fa.x + fa.y + boA;
            out[base + cz2 + 64] = fb.x + fb.y + boB;
        }
    }
}

extern "C" void kernel_launch(void* const* d_in, const int* in_sizes, int n_in,
                              void* d_out, int out_size) {
    const float* x  = (const float*)d_in[0];
    const float* nw = (const float*)d_in[1];
    const float* nb = (const float*)d_in[2];
    const float* Wa = (const float*)d_in[3];
    const float* Wb = (const float*)d_in[4];
    const float* Wo = (const float*)d_in[5];
    const float* bo = (const float*)d_in[6];
    float* out = (float*)d_out;

    cudaFuncSetAttribute(ln_proj_kernel, cudaFuncAttributeMaxDynamicSharedMemorySize, K1_SMEM);
    cudaFuncSetAttribute(opm_kernel,     cudaFuncAttributeMaxDynamicSharedMemorySize, K2_SMEM);

    ln_proj_kernel<<<NROWS / 8, 256, K1_SMEM>>>(x, nw, nb, Wa, Wb);
    dim3 grid(128, 128);
    opm_kernel<<<grid, 256, K2_SMEM>>>(Wo, bo, out);
}

// round 7
// speedup vs baseline: 2.3007x; 2.0759x over previous
#include <cuda_runtime.h>
#include <cuda_bf16.h>
#include <cstdint>

// Problem: S=128, I=J=512, CM=256, C=D=32, CZ=128
// opm CTA = 4i x 8j pairs; grid (64 jt, 128 it).
// Phase A: D[128m x 256n] = sum over K=384 (bf16 3-term split of K=128 s)
// Phase B: Z[128cz x 32p], K = 16kt x 3 terms x 64k

// ---------------- smem layout (bytes) ----------------
#define ABUF(b)   ((b) * 55296)
#define BOFF      18432
#define OHI       0
#define OLO       66048
#define OSTRIDE   2064
#define WO_OFF    132096
#define WOBUF_SZ  36864
#define TSTRIDE   144
#define SMEM2     205824
#define K1_SMEM   ((2*32*260 + 8*256) * 4)

// Pre-tiled globals (plain [row][64k] bf16 tiles):
// g_A3: (it 0..127, kt 0..5): [128 m][64 k]
// g_B3: (jt 0..63,  kt 0..5): [256 n][64 k]
// g_Wo3: kt 0..15 = hi tiles [128 cz][64 k], kt 16..31 = lo tiles
__device__ __align__(256) __nv_bfloat16 g_A3[128 * 6 * 8192];
__device__ __align__(256) __nv_bfloat16 g_B3[64 * 6 * 16384];
__device__ __align__(256) __nv_bfloat16 g_Wo3[32 * 8192];

// ---------------- helpers ----------------
__device__ __forceinline__ uint32_t smem_u32(const void* p) {
    uint32_t a;
    asm("{ .reg .u64 t; cvta.to.shared.u64 t, %1; cvt.u32.u64 %0, t; }" : "=r"(a) : "l"(p));
    return a;
}
__device__ __forceinline__ void cp16(uint32_t smdst, const void* src) {
    asm volatile("cp.async.cg.shared.global [%0], [%1], 16;" :: "r"(smdst), "l"(src));
}
__device__ __forceinline__ void cp_commit() { asm volatile("cp.async.commit_group;"); }
template<int N> __device__ __forceinline__ void cp_wait() {
    asm volatile("cp.async.wait_group %0;" :: "n"(N));
}
__device__ __forceinline__ void ldm_x4(uint32_t* r, uint32_t addr) {
    asm volatile("ldmatrix.sync.aligned.m8n8.x4.shared.b16 {%0,%1,%2,%3}, [%4];"
                 : "=r"(r[0]), "=r"(r[1]), "=r"(r[2]), "=r"(r[3]) : "r"(addr));
}
__device__ __forceinline__ void mma16816(float* d, const uint32_t* a, uint32_t b0, uint32_t b1) {
    asm volatile(
        "mma.sync.aligned.m16n8k16.row.col.f32.bf16.bf16.f32 "
        "{%0,%1,%2,%3}, {%4,%5,%6,%7}, {%8,%9}, {%0,%1,%2,%3};"
        : "+f"(d[0]), "+f"(d[1]), "+f"(d[2]), "+f"(d[3])
        : "r"(a[0]), "r"(a[1]), "r"(a[2]), "r"(a[3]), "r"(b0), "r"(b1));
}
__device__ __forceinline__ uint32_t packbf(float lo, float hi) {  // lo -> low half
    uint32_t r;
    asm("cvt.rn.satfinite.bf16x2.f32 %0, %1, %2;" : "=r"(r) : "f"(hi), "f"(lo));
    return r;
}
// stage contiguous [rows][64] bf16 tile into smem with TSTRIDE-padded rows
__device__ __forceinline__ void stage_tile(uint32_t smdst, const __nv_bfloat16* g, int rows, int t) {
    const char* s = (const char*)g;
    for (int idx = t; idx < rows * 8; idx += 256) {
        int r = idx >> 3, c = idx & 7;
        cp16(smdst + r * TSTRIDE + c * 16, s + r * 128 + c * 16);
    }
}

// =====================================================================
// Kernel 0: split Wo into hi/lo tiled global.
// =====================================================================
__global__ void wo_prep_kernel(const float* __restrict__ Wo) {
    int idx = blockIdx.x * 256 + threadIdx.x;      // 131072
    int cz = idx >> 10, k = idx & 1023;
    int kt = k >> 6, kk = k & 63;
    float w = Wo[idx];
    __nv_bfloat16 h = __float2bfloat16(w);
    __nv_bfloat16 l = __float2bfloat16(w - __bfloat162float(h));
    g_Wo3[kt * 8192 + cz * 64 + kk]        = h;
    g_Wo3[(16 + kt) * 8192 + cz * 64 + kk] = l;
}

// =====================================================================
// Kernel 1: LayerNorm + dual projection -> bf16 hi/lo pre-tiled globals.
// =====================================================================
__global__ __launch_bounds__(256, 2)
void ln_proj_kernel(const float* __restrict__ x,
                    const float* __restrict__ nw,
                    const float* __restrict__ nb,
                    const float* __restrict__ Wa,
                    const float* __restrict__ Wb)
{
    extern __shared__ float sm[];
    float* Wa_s = sm;                 // [32][260]
    float* Wb_s = sm + 32 * 260;
    float* ln_s = sm + 2 * 32 * 260;  // [8][256]

    const int t = threadIdx.x, lane = t & 31, w = t >> 5;

    for (int idx = t; idx < 8192; idx += 256) {
        int c = idx >> 8, m = idx & 255;
        Wa_s[c * 260 + m] = Wa[idx];
        Wb_s[c * 260 + m] = Wb[idx];
    }

    const int row = blockIdx.x * 8 + w;
    const float* xr = x + (size_t)row * 256;

    float v[8]; float s = 0.f, sq = 0.f;
    #pragma unroll
    for (int h = 0; h < 2; h++) {
        float4 x4 = *(const float4*)(xr + lane * 4 + 128 * h);
        v[h*4+0]=x4.x; v[h*4+1]=x4.y; v[h*4+2]=x4.z; v[h*4+3]=x4.w;
        s  += x4.x + x4.y + x4.z + x4.w;
        sq += x4.x*x4.x + x4.y*x4.y + x4.z*x4.z + x4.w*x4.w;
    }
    #pragma unroll
    for (int o = 16; o > 0; o >>= 1) {
        s  += __shfl_xor_sync(0xffffffffu, s,  o);
        sq += __shfl_xor_sync(0xffffffffu, sq, o);
    }
    float mu  = s * (1.f / 256.f);
    float var = sq * (1.f / 256.f) - mu * mu;
    float rs  = rsqrtf(var + 1e-5f);
    #pragma unroll
    for (int h = 0; h < 2; h++) {
        int m0 = lane * 4 + 128 * h;
        float4 w4 = *(const float4*)(nw + m0);
        float4 b4 = *(const float4*)(nb + m0);
        float* lp = ln_s + w * 256 + m0;
        lp[0] = (v[h*4+0]-mu)*rs*w4.x + b4.x;
        lp[1] = (v[h*4+1]-mu)*rs*w4.y + b4.y;
        lp[2] = (v[h*4+2]-mu)*rs*w4.z + b4.z;
        lp[3] = (v[h*4+3]-mu)*rs*w4.w + b4.w;
    }
    __syncthreads();

    float accA = 0.f, accB = 0.f;
    const float* lr  = ln_s + w * 256;
    const float* war = Wa_s + lane * 260;
    const float* wbr = Wb_s + lane * 260;
    #pragma unroll 8
    for (int m4 = 0; m4 < 64; m4++) {
        float4 l4  = *(const float4*)(lr  + m4 * 4);
        float4 wa4 = *(const float4*)(war + m4 * 4);
        float4 wb4 = *(const float4*)(wbr + m4 * 4);
        accA = fmaf(l4.x, wa4.x, accA); accA = fmaf(l4.y, wa4.y, accA);
        accA = fmaf(l4.z, wa4.z, accA); accA = fmaf(l4.w, wa4.w, accA);
        accB = fmaf(l4.x, wb4.x, accB); accB = fmaf(l4.y, wb4.y, accB);
        accB = fmaf(l4.z, wb4.z, accB); accB = fmaf(l4.w, wb4.w, accB);
    }

    // split + scatter: row = s*512 + ij
    __nv_bfloat16 ah = __float2bfloat16(accA);
    __nv_bfloat16 al = __float2bfloat16(accA - __bfloat162float(ah));
    __nv_bfloat16 bh = __float2bfloat16(accB);
    __nv_bfloat16 bl = __float2bfloat16(accB - __bfloat162float(bh));
    const int ss = row >> 9, ij = row & 511;
    const int kts = ss >> 6, kk = ss & 63;
    {   // A terms: kt = kts(ahi), 2+kts(ahi), 4+kts(alo)
        int it = ij >> 2, m = (ij & 3) * 32 + lane;
        __nv_bfloat16* base = g_A3 + (size_t)(it * 6) * 8192 + m * 64 + kk;
        base[(size_t)kts * 8192]       = ah;
        base[(size_t)(2 + kts) * 8192] = ah;
        base[(size_t)(4 + kts) * 8192] = al;
    }
    {   // B terms: bhi, blo, bhi
        int jt = ij >> 3, n = (ij & 7) * 32 + lane;
        __nv_bfloat16* base = g_B3 + (size_t)(jt * 6) * 16384 + n * 64 + kk;
        base[(size_t)kts * 16384]       = bh;
        base[(size_t)(2 + kts) * 16384] = bl;
        base[(size_t)(4 + kts) * 16384] = bh;
    }
}

// =====================================================================
// Kernel 2: fused OPM + projection via mma.sync bf16.
// =====================================================================
__global__ __launch_bounds__(256, 1)
void opm_kernel(const float* __restrict__ bo, float* __restrict__ out)
{
    extern __shared__ char smc[];
    const uint32_t sb = smem_u32(smc);
    const int t = threadIdx.x, lane = t & 31, wid = t >> 5;
    const int jt = blockIdx.x, it = blockIdx.y;

    const __nv_bfloat16* Abase = g_A3 + (size_t)(it * 6) * 8192;
    const __nv_bfloat16* Bbase = g_B3 + (size_t)(jt * 6) * 16384;

    // prologue: AB0, AB1, Wo0
    stage_tile(sb + ABUF(0),        Abase,         128, t);
    stage_tile(sb + ABUF(0) + BOFF, Bbase,         256, t);
    cp_commit();
    stage_tile(sb + ABUF(1),        Abase + 8192,  128, t);
    stage_tile(sb + ABUF(1) + BOFF, Bbase + 16384, 256, t);
    cp_commit();
    stage_tile(sb + WO_OFF,         g_Wo3,             128, t);
    stage_tile(sb + WO_OFF + 18432, g_Wo3 + 16 * 8192, 128, t);
    cp_commit();

    // ---------------- Phase A ----------------
    const int wm = wid & 1, wn = wid >> 1;
    const uint32_t lrow  = (uint32_t)(lane & 15) * TSTRIDE;
    const uint32_t lcol  = (uint32_t)(lane >> 4) * 16;
    float acc[4][8][4];
    #pragma unroll
    for (int mt = 0; mt < 4; mt++)
        #pragma unroll
        for (int nt = 0; nt < 8; nt++)
            #pragma unroll
            for (int e = 0; e < 4; e++) acc[mt][nt][e] = 0.f;

    #pragma unroll 1
    for (int kt = 0; kt < 6; kt++) {
        if (kt < 2) cp_wait<2>(); else cp_wait<1>();
        __syncthreads();
        const uint32_t ab = sb + ABUF(kt & 1);
        const uint32_t aB = ab + (uint32_t)(wm * 64) * TSTRIDE + lrow + lcol;
        const uint32_t bB = ab + BOFF + (uint32_t)(wn * 64) * TSTRIDE + lrow + lcol;
        #pragma unroll
        for (int k16 = 0; k16 < 4; k16++) {
            uint32_t A4[4][4], B4[4][4];
            #pragma unroll
            for (int mt = 0; mt < 4; mt++) ldm_x4(A4[mt], aB + mt * 16 * TSTRIDE + k16 * 32);
            #pragma unroll
            for (int bt = 0; bt < 4; bt++) ldm_x4(B4[bt], bB + bt * 16 * TSTRIDE + k16 * 32);
            #pragma unroll
            for (int mt = 0; mt < 4; mt++)
                #pragma unroll
                for (int bt = 0; bt < 4; bt++) {
                    mma16816(acc[mt][bt*2],   A4[mt], B4[bt][0], B4[bt][2]);
                    mma16816(acc[mt][bt*2+1], A4[mt], B4[bt][1], B4[bt][3]);
                }
        }
        __syncthreads();
        if (kt < 4) {
            stage_tile(sb + ABUF(kt & 1),        Abase + (size_t)(kt+2) * 8192,  128, t);
            stage_tile(sb + ABUF(kt & 1) + BOFF, Bbase + (size_t)(kt+2) * 16384, 256, t);
            cp_commit();
        } else if (kt == 4) {
            stage_tile(sb + WO_OFF + WOBUF_SZ,         g_Wo3 + 8192,             128, t);
            stage_tile(sb + WO_OFF + WOBUF_SZ + 18432, g_Wo3 + (16 + 1) * 8192,  128, t);
            cp_commit();
        }
    }

    // ---------------- Epilogue: accums -> O hi/lo smem ----------------
    {
        const int m0 = wm * 64, n0 = wn * 64;
        const int mr = lane >> 2, nc = (lane & 3) * 2;
        #pragma unroll
        for (int mt = 0; mt < 4; mt++)
            #pragma unroll
            for (int nt = 0; nt < 8; nt++) {
                #pragma unroll
                for (int h = 0; h < 2; h++) {
                    int m = m0 + mt * 16 + mr + h * 8;
                    int n = n0 + nt * 8 + nc;
                    float f0 = acc[mt][nt][2*h]   * (1.f / 128.f);
                    float f1 = acc[mt][nt][2*h+1] * (1.f / 128.f);
                    float h0 = __bfloat162float(__float2bfloat16(f0));
                    float h1 = __bfloat162float(__float2bfloat16(f1));
                    uint32_t hi = packbf(f0, f1);
                    uint32_t lo = packbf(f0 - h0, f1 - h1);
                    int p = (m >> 5) * 8 + (n >> 5);
                    int k = (m & 31) * 32 + (n & 31);
                    uint32_t off = (uint32_t)(p * OSTRIDE + k * 2);
                    asm volatile("st.shared.b32 [%0], %1;" :: "r"(sb + OHI + off), "r"(hi) : "memory");
                    asm volatile("st.shared.b32 [%0], %1;" :: "r"(sb + OLO + off), "r"(lo) : "memory");
                }
            }
    }
    __syncthreads();

    // ---------------- Phase B ----------------
    float z[4][4];
    #pragma unroll
    for (int nt = 0; nt < 4; nt++)
        #pragma unroll
        for (int e = 0; e < 4; e++) z[nt][e] = 0.f;

    const int czt = wid * 16;
    const uint32_t oHiB = sb + OHI + (uint32_t)(lane & 15) * OSTRIDE + lcol;
    const uint32_t oLoB = oHiB + (OLO - OHI);

    #pragma unroll 1
    for (int kt = 0; kt < 16; kt++) {
        cp_wait<1>();
        __syncthreads();
        const uint32_t wbuf = sb + WO_OFF + (kt & 1) * WOBUF_SZ;
        const uint32_t wB = wbuf + (uint32_t)czt * TSTRIDE + lrow + lcol;
        const uint32_t kb0 = (uint32_t)kt * 128;   // O tiles only (1024-k rows)
        #pragma unroll
        for (int term = 0; term < 3; term++) {
            const uint32_t wb = wB + (term == 2 ? 18432u : 0u);
            const uint32_t ob = (term == 1) ? oLoB : oHiB;
            #pragma unroll
            for (int k16 = 0; k16 < 4; k16++) {
                uint32_t A4[4], B0[4], B1[4];
                ldm_x4(A4, wb + k16 * 32);                        // Wo buf holds ONE kt tile
                ldm_x4(B0, ob + kb0 + k16 * 32);
                ldm_x4(B1, ob + 16 * OSTRIDE + kb0 + k16 * 32);
                mma16816(z[0], A4, B0[0], B0[2]);
                mma16816(z[1], A4, B0[1], B0[3]);
                mma16816(z[2], A4, B1[0], B1[2]);
                mma16816(z[3], A4, B1[1], B1[3]);
            }
        }
        __syncthreads();
        if (kt + 2 < 16) {
            stage_tile(sb + WO_OFF + (kt & 1) * WOBUF_SZ,         g_Wo3 + (size_t)(kt+2) * 8192,    128, t);
            stage_tile(sb + WO_OFF + (kt & 1) * WOBUF_SZ + 18432, g_Wo3 + (size_t)(16+kt+2) * 8192, 128, t);
        }
        cp_commit();
    }

    // ---------------- Writeout via smem ----------------
    __syncthreads();
    float* zs = (float*)(smc + WO_OFF);   // [32][132]
    {
        const int mr = lane >> 2, nc = (lane & 3) * 2;
        #pragma unroll
        for (int nt = 0; nt < 4; nt++)
            #pragma unroll
            for (int e = 0; e < 4; e++) {
                int cz = czt + mr + (e >> 1) * 8;
                int pr = nt * 8 + nc + (e & 1);
                zs[pr * 132 + cz] = z[nt][e];
            }
    }
    __syncthreads();
    #pragma unroll
    for (int q = 0; q < 16; q++) {
        int idx = q * 256 + t;
        int pr = idx >> 7, cz = idx & 127;
        out[((it * 4 + (pr >> 3)) * 512 + jt * 8 + (pr & 7)) * 128 + cz]
            = zs[pr * 132 + cz] + bo[cz];
    }
}

extern "C" void kernel_launch(void* const* d_in, const int* in_sizes, int n_in,
                              void* d_out, int out_size) {
    const float* x  = (const float*)d_in[0];
    const float* nw = (const float*)d_in[1];
    const float* nb = (const float*)d_in[2];
    const float* Wa = (const float*)d_in[3];
    const float* Wb = (const float*)d_in[4];
    const float* Wo = (const float*)d_in[5];
    const float* bo = (const float*)d_in[6];
    float* out = (float*)d_out;

    cudaFuncSetAttribute(ln_proj_kernel, cudaFuncAttributeMaxDynamicSharedMemorySize, K1_SMEM);
    cudaFuncSetAttribute(opm_kernel,     cudaFuncAttributeMaxDynamicSharedMemorySize, SMEM2);

    wo_prep_kernel<<<512, 256>>>(Wo);
    ln_proj_kernel<<<65536 / 8, 256, K1_SMEM>>>(x, nw, nb, Wa, Wb);
    opm_kernel<<<dim3(64, 128), 256, SMEM2>>>(bo, out);
}

// round 8
// speedup vs baseline: 2.4181x; 1.0510x over previous
#include <cuda_runtime.h>
#include <cuda_bf16.h>
#include <cstdint>

// Problem: S=128, I=J=512, CM=256, C=D=32, CZ=128
// opm CTA = 4i x 8j pairs; grid (64 jt, 128 it); 512 threads.
// Phase A: D[128m x 256n], K=384 (bf16 3-term split).  16 warps, tile 32x64.
// Phase B: Z[128cz x 32p], K=16kt x 3terms x 64k. 2 groups of 8 warps split kt parity.

// ---------------- smem layout (bytes) ----------------
#define ABUF(b)   ((b) * 55296)
#define BOFF      18432
#define OHI       0
#define OLO       66048
#define OSTRIDE   2064
#define WO_OFF    132096
#define WOBUF_SZ  36864     // one group's buffer: hi 18432 + lo 18432
#define TSTRIDE   144
#define SMEM2     205824
#define K1_SMEM   ((2*32*260 + 8*256) * 4)

// Pre-tiled globals (plain [row][64k] bf16 tiles):
__device__ __align__(256) __nv_bfloat16 g_A3[128 * 6 * 8192];
__device__ __align__(256) __nv_bfloat16 g_B3[64 * 6 * 16384];
__device__ __align__(256) __nv_bfloat16 g_Wo3[32 * 8192];   // kt0-15 hi, 16-31 lo

// ---------------- helpers ----------------
__device__ __forceinline__ uint32_t smem_u32(const void* p) {
    uint32_t a;
    asm("{ .reg .u64 t; cvta.to.shared.u64 t, %1; cvt.u32.u64 %0, t; }" : "=r"(a) : "l"(p));
    return a;
}
__device__ __forceinline__ void cp16(uint32_t smdst, const void* src) {
    asm volatile("cp.async.cg.shared.global [%0], [%1], 16;" :: "r"(smdst), "l"(src));
}
__device__ __forceinline__ void cp_commit() { asm volatile("cp.async.commit_group;"); }
template<int N> __device__ __forceinline__ void cp_wait() {
    asm volatile("cp.async.wait_group %0;" :: "n"(N));
}
__device__ __forceinline__ void barx(int id) {
    asm volatile("bar.sync %0, 256;" :: "r"(id) : "memory");
}
__device__ __forceinline__ void ldm_x4(uint32_t* r, uint32_t addr) {
    asm volatile("ldmatrix.sync.aligned.m8n8.x4.shared.b16 {%0,%1,%2,%3}, [%4];"
                 : "=r"(r[0]), "=r"(r[1]), "=r"(r[2]), "=r"(r[3]) : "r"(addr));
}
__device__ __forceinline__ void mma16816(float* d, const uint32_t* a, uint32_t b0, uint32_t b1) {
    asm volatile(
        "mma.sync.aligned.m16n8k16.row.col.f32.bf16.bf16.f32 "
        "{%0,%1,%2,%3}, {%4,%5,%6,%7}, {%8,%9}, {%0,%1,%2,%3};"
        : "+f"(d[0]), "+f"(d[1]), "+f"(d[2]), "+f"(d[3])
        : "r"(a[0]), "r"(a[1]), "r"(a[2]), "r"(a[3]), "r"(b0), "r"(b1));
}
__device__ __forceinline__ uint32_t packbf(float lo, float hi) {  // lo -> low half
    uint32_t r;
    asm("cvt.rn.satfinite.bf16x2.f32 %0, %1, %2;" : "=r"(r) : "f"(hi), "f"(lo));
    return r;
}
// stage contiguous [rows][64] bf16 tile into smem (TSTRIDE-padded rows)
__device__ __forceinline__ void stage_tile(uint32_t smdst, const __nv_bfloat16* g,
                                           int rows, int t, int nthr) {
    const char* s = (const char*)g;
    for (int idx = t; idx < rows * 8; idx += nthr) {
        int r = idx >> 3, c = idx & 7;
        cp16(smdst + r * TSTRIDE + c * 16, s + r * 128 + c * 16);
    }
}

// =====================================================================
// Kernel 0: split Wo into hi/lo tiled global.
// =====================================================================
__global__ void wo_prep_kernel(const float* __restrict__ Wo) {
    int idx = blockIdx.x * 256 + threadIdx.x;      // 131072
    int cz = idx >> 10, k = idx & 1023;
    int kt = k >> 6, kk = k & 63;
    float w = Wo[idx];
    __nv_bfloat16 h = __float2bfloat16(w);
    __nv_bfloat16 l = __float2bfloat16(w - __bfloat162float(h));
    g_Wo3[kt * 8192 + cz * 64 + kk]        = h;
    g_Wo3[(16 + kt) * 8192 + cz * 64 + kk] = l;
}

// =====================================================================
// Kernel 1: LayerNorm + dual projection -> bf16 hi/lo pre-tiled globals.
// =====================================================================
__global__ __launch_bounds__(256, 2)
void ln_proj_kernel(const float* __restrict__ x,
                    const float* __restrict__ nw,
                    const float* __restrict__ nb,
                    const float* __restrict__ Wa,
                    const float* __restrict__ Wb)
{
    extern __shared__ float sm[];
    float* Wa_s = sm;                 // [32][260]
    float* Wb_s = sm + 32 * 260;
    float* ln_s = sm + 2 * 32 * 260;  // [8][256]

    const int t = threadIdx.x, lane = t & 31, w = t >> 5;

    for (int idx = t; idx < 8192; idx += 256) {
        int c = idx >> 8, m = idx & 255;
        Wa_s[c * 260 + m] = Wa[idx];
        Wb_s[c * 260 + m] = Wb[idx];
    }

    const int row = blockIdx.x * 8 + w;
    const float* xr = x + (size_t)row * 256;

    float v[8]; float s = 0.f, sq = 0.f;
    #pragma unroll
    for (int h = 0; h < 2; h++) {
        float4 x4 = *(const float4*)(xr + lane * 4 + 128 * h);
        v[h*4+0]=x4.x; v[h*4+1]=x4.y; v[h*4+2]=x4.z; v[h*4+3]=x4.w;
        s  += x4.x + x4.y + x4.z + x4.w;
        sq += x4.x*x4.x + x4.y*x4.y + x4.z*x4.z + x4.w*x4.w;
    }
    #pragma unroll
    for (int o = 16; o > 0; o >>= 1) {
        s  += __shfl_xor_sync(0xffffffffu, s,  o);
        sq += __shfl_xor_sync(0xffffffffu, sq, o);
    }
    float mu  = s * (1.f / 256.f);
    float var = sq * (1.f / 256.f) - mu * mu;
    float rs  = rsqrtf(var + 1e-5f);
    #pragma unroll
    for (int h = 0; h < 2; h++) {
        int m0 = lane * 4 + 128 * h;
        float4 w4 = *(const float4*)(nw + m0);
        float4 b4 = *(const float4*)(nb + m0);
        float* lp = ln_s + w * 256 + m0;
        lp[0] = (v[h*4+0]-mu)*rs*w4.x + b4.x;
        lp[1] = (v[h*4+1]-mu)*rs*w4.y + b4.y;
        lp[2] = (v[h*4+2]-mu)*rs*w4.z + b4.z;
        lp[3] = (v[h*4+3]-mu)*rs*w4.w + b4.w;
    }
    __syncthreads();

    float accA = 0.f, accB = 0.f;
    const float* lr  = ln_s + w * 256;
    const float* war = Wa_s + lane * 260;
    const float* wbr = Wb_s + lane * 260;
    #pragma unroll 8
    for (int m4 = 0; m4 < 64; m4++) {
        float4 l4  = *(const float4*)(lr  + m4 * 4);
        float4 wa4 = *(const float4*)(war + m4 * 4);
        float4 wb4 = *(const float4*)(wbr + m4 * 4);
        accA = fmaf(l4.x, wa4.x, accA); accA = fmaf(l4.y, wa4.y, accA);
        accA = fmaf(l4.z, wa4.z, accA); accA = fmaf(l4.w, wa4.w, accA);
        accB = fmaf(l4.x, wb4.x, accB); accB = fmaf(l4.y, wb4.y, accB);
        accB = fmaf(l4.z, wb4.z, accB); accB = fmaf(l4.w, wb4.w, accB);
    }

    __nv_bfloat16 ah = __float2bfloat16(accA);
    __nv_bfloat16 al = __float2bfloat16(accA - __bfloat162float(ah));
    __nv_bfloat16 bh = __float2bfloat16(accB);
    __nv_bfloat16 bl = __float2bfloat16(accB - __bfloat162float(bh));
    const int ss = row >> 9, ij = row & 511;
    const int kts = ss >> 6, kk = ss & 63;
    {   // A terms: kt = kts(ahi), 2+kts(ahi), 4+kts(alo)
        int it = ij >> 2, m = (ij & 3) * 32 + lane;
        __nv_bfloat16* base = g_A3 + (size_t)(it * 6) * 8192 + m * 64 + kk;
        base[(size_t)kts * 8192]       = ah;
        base[(size_t)(2 + kts) * 8192] = ah;
        base[(size_t)(4 + kts) * 8192] = al;
    }
    {   // B terms: bhi, blo, bhi
        int jt = ij >> 3, n = (ij & 7) * 32 + lane;
        __nv_bfloat16* base = g_B3 + (size_t)(jt * 6) * 16384 + n * 64 + kk;
        base[(size_t)kts * 16384]       = bh;
        base[(size_t)(2 + kts) * 16384] = bl;
        base[(size_t)(4 + kts) * 16384] = bh;
    }
}

// =====================================================================
// Kernel 2: fused OPM + projection, 512 threads.
// =====================================================================
__global__ __launch_bounds__(512, 1)
void opm_kernel(const float* __restrict__ bo, float* __restrict__ out)
{
    extern __shared__ char smc[];
    const uint32_t sb = smem_u32(smc);
    const int t = threadIdx.x, lane = t & 31, wid = t >> 5;
    const int jt = blockIdx.x, it = blockIdx.y;
    const int g  = wid >> 3;              // phase-B group (kt parity)

    const __nv_bfloat16* Abase = g_A3 + (size_t)(it * 6) * 8192;
    const __nv_bfloat16* Bbase = g_B3 + (size_t)(jt * 6) * 16384;

    // ---- prologue ----
    // per-thread commit sequence: c0=AB0, c1=AB1, c2=Wo(g), c3..c6=AB2..AB5
    stage_tile(sb + ABUF(0),        Abase,         128, t, 512);
    stage_tile(sb + ABUF(0) + BOFF, Bbase,         256, t, 512);
    cp_commit();                                                    // c0
    stage_tile(sb + ABUF(1),        Abase + 8192,  128, t, 512);
    stage_tile(sb + ABUF(1) + BOFF, Bbase + 16384, 256, t, 512);
    cp_commit();                                                    // c1
    {   // group g stages Wo(kt=g) into its own buffer with its 256 threads
        const int gt = t & 255;
        uint32_t wb = sb + WO_OFF + g * WOBUF_SZ;
        stage_tile(wb,         g_Wo3 + (size_t)g * 8192,        128, gt, 256);
        stage_tile(wb + 18432, g_Wo3 + (size_t)(16 + g) * 8192, 128, gt, 256);
        cp_commit();                                                // c2
    }

    // ---- Phase A: 16 warps, 4x4 grid of 32m x 64n tiles ----
    const int wm = wid & 3, wn = wid >> 2;
    const uint32_t lrow = (uint32_t)(lane & 15) * TSTRIDE;
    const uint32_t lcol = (uint32_t)(lane >> 4) * 16;
    float acc[2][8][4];
    #pragma unroll
    for (int mt = 0; mt < 2; mt++)
        #pragma unroll
        for (int nt = 0; nt < 8; nt++)
            #pragma unroll
            for (int e = 0; e < 4; e++) acc[mt][nt][e] = 0.f;

    #pragma unroll 1
    for (int kt = 0; kt < 6; kt++) {
        // need AB_kt: waits audited -> kt<2: wait<2>; 2<=kt<5: wait<1>; kt=5: wait<0>
        if (kt < 2) cp_wait<2>(); else if (kt < 5) cp_wait<1>(); else cp_wait<0>();
        __syncthreads();
        const uint32_t ab = sb + ABUF(kt & 1);
        const uint32_t aB = ab + (uint32_t)(wm * 32) * TSTRIDE + lrow + lcol;
        const uint32_t bB = ab + BOFF + (uint32_t)(wn * 64) * TSTRIDE + lrow + lcol;
        #pragma unroll
        for (int k16 = 0; k16 < 4; k16++) {
            uint32_t A4[2][4], B4[4][4];
            #pragma unroll
            for (int mt = 0; mt < 2; mt++) ldm_x4(A4[mt], aB + mt * 16 * TSTRIDE + k16 * 32);
            #pragma unroll
            for (int bt = 0; bt < 4; bt++) ldm_x4(B4[bt], bB + bt * 16 * TSTRIDE + k16 * 32);
            #pragma unroll
            for (int mt = 0; mt < 2; mt++)
                #pragma unroll
                for (int bt = 0; bt < 4; bt++) {
                    mma16816(acc[mt][bt*2],   A4[mt], B4[bt][0], B4[bt][2]);
                    mma16816(acc[mt][bt*2+1], A4[mt], B4[bt][1], B4[bt][3]);
                }
        }
        __syncthreads();
        if (kt < 4) {
            stage_tile(sb + ABUF(kt & 1),        Abase + (size_t)(kt+2) * 8192,  128, t, 512);
            stage_tile(sb + ABUF(kt & 1) + BOFF, Bbase + (size_t)(kt+2) * 16384, 256, t, 512);
            cp_commit();                                            // c3..c6
        }
    }

    // ---- Epilogue: accums -> O hi/lo smem ----
    {
        const int m0 = wm * 32, n0 = wn * 64;
        const int mr = lane >> 2, nc = (lane & 3) * 2;
        #pragma unroll
        for (int mt = 0; mt < 2; mt++)
            #pragma unroll
            for (int nt = 0; nt < 8; nt++) {
                #pragma unroll
                for (int h = 0; h < 2; h++) {
                    int m = m0 + mt * 16 + mr + h * 8;
                    int n = n0 + nt * 8 + nc;
                    float f0 = acc[mt][nt][2*h]   * (1.f / 128.f);
                    float f1 = acc[mt][nt][2*h+1] * (1.f / 128.f);
                    float h0 = __bfloat162float(__float2bfloat16(f0));
                    float h1 = __bfloat162float(__float2bfloat16(f1));
                    uint32_t hi = packbf(f0, f1);
                    uint32_t lo = packbf(f0 - h0, f1 - h1);
                    int p = (m >> 5) * 8 + (n >> 5);
                    int k = (m & 31) * 32 + (n & 31);
                    uint32_t off = (uint32_t)(p * OSTRIDE + k * 2);
                    asm volatile("st.shared.b32 [%0], %1;" :: "r"(sb + OHI + off), "r"(hi) : "memory");
                    asm volatile("st.shared.b32 [%0], %1;" :: "r"(sb + OLO + off), "r"(lo) : "memory");
                }
            }
    }
    __syncthreads();

    // ---- Phase B: group g handles kt = g, g+2, ..., g+14 ----
    float z[4][4];
    #pragma unroll
    for (int nt = 0; nt < 4; nt++)
        #pragma unroll
        for (int e = 0; e < 4; e++) z[nt][e] = 0.f;

    const int wg  = wid & 7;
    const int czt = wg * 16;
    const int gt  = t & 255;
    const uint32_t wbuf = sb + WO_OFF + g * WOBUF_SZ;
    const uint32_t wB   = wbuf + (uint32_t)czt * TSTRIDE + lrow + lcol;

    #pragma unroll 1
    for (int s = 0; s < 8; s++) {
        const int kt = g + 2 * s;
        cp_wait<0>();                 // this group's Wo(kt) landed
        barx(1 + g);
        const uint32_t kb = (uint32_t)kt * 128;
        const uint32_t oHi = sb + OHI + (uint32_t)(lane & 15) * OSTRIDE + lcol + kb;
        const uint32_t oLo = oHi + (OLO - OHI);
        #pragma unroll
        for (int k16 = 0; k16 < 4; k16++) {
            uint32_t Whi[4], Wlo[4], OhA[4], OhB[4], OlA[4], OlB[4];
            ldm_x4(Whi, wB + k16 * 32);
            ldm_x4(Wlo, wB + 18432 + k16 * 32);
            ldm_x4(OhA, oHi + k16 * 32);
            ldm_x4(OhB, oHi + 16 * OSTRIDE + k16 * 32);
            ldm_x4(OlA, oLo + k16 * 32);
            ldm_x4(OlB, oLo + 16 * OSTRIDE + k16 * 32);
            // whi*Ohi
            mma16816(z[0], Whi, OhA[0], OhA[2]); mma16816(z[1], Whi, OhA[1], OhA[3]);
            mma16816(z[2], Whi, OhB[0], OhB[2]); mma16816(z[3], Whi, OhB[1], OhB[3]);
            // whi*Olo
            mma16816(z[0], Whi, OlA[0], OlA[2]); mma16816(z[1], Whi, OlA[1], OlA[3]);
            mma16816(z[2], Whi, OlB[0], OlB[2]); mma16816(z[3], Whi, OlB[1], OlB[3]);
            // wlo*Ohi
            mma16816(z[0], Wlo, OhA[0], OhA[2]); mma16816(z[1], Wlo, OhA[1], OhA[3]);
            mma16816(z[2], Wlo, OhB[0], OhB[2]); mma16816(z[3], Wlo, OhB[1], OhB[3]);
        }
        barx(1 + g);
        if (s < 7) {
            stage_tile(wbuf,         g_Wo3 + (size_t)(kt + 2) * 8192,      128, gt, 256);
            stage_tile(wbuf + 18432, g_Wo3 + (size_t)(16 + kt + 2) * 8192, 128, gt, 256);
            cp_commit();
        }
    }

    // ---- reduce group partials + writeout ----
    __syncthreads();
    float* zs = (float*)(smc + WO_OFF);   // [32][132] floats (reuses group-0 buf)
    {
        const int mr = lane >> 2, nc = (lane & 3) * 2;
        if (g == 1) {
            #pragma unroll
            for (int nt = 0; nt < 4; nt++)
                #pragma unroll
                for (int e = 0; e < 4; e++) {
                    int cz = czt + mr + (e >> 1) * 8;
                    int pr = nt * 8 + nc + (e & 1);
                    zs[pr * 132 + cz] = z[nt][e];
                }
        }
        __syncthreads();
        if (g == 0) {
            #pragma unroll
            for (int nt = 0; nt < 4; nt++)
                #pragma unroll
                for (int e = 0; e < 4; e++) {
                    int cz = czt + mr + (e >> 1) * 8;
                    int pr = nt * 8 + nc + (e & 1);
                    zs[pr * 132 + cz] += z[nt][e];
                }
        }
    }
    __syncthreads();
    #pragma unroll
    for (int q = 0; q < 8; q++) {
        int idx = q * 512 + t;
        int pr = idx >> 7, cz = idx & 127;
        out[((it * 4 + (pr >> 3)) * 512 + jt * 8 + (pr & 7)) * 128 + cz]
            = zs[pr * 132 + cz] + bo[cz];
    }
}

extern "C" void kernel_launch(void* const* d_in, const int* in_sizes, int n_in,
                              void* d_out, int out_size) {
    const float* x  = (const float*)d_in[0];
    const float* nw = (const float*)d_in[1];
    const float* nb = (const float*)d_in[2];
    const float* Wa = (const float*)d_in[3];
    const float* Wb = (const float*)d_in[4];
    const float* Wo = (const float*)d_in[5];
    const float* bo = (const float*)d_in[6];
    float* out = (float*)d_out;

    cudaFuncSetAttribute(ln_proj_kernel, cudaFuncAttributeMaxDynamicSharedMemorySize, K1_SMEM);
    cudaFuncSetAttribute(opm_kernel,     cudaFuncAttributeMaxDynamicSharedMemorySize, SMEM2);

    wo_prep_kernel<<<512, 256>>>(Wo);
    ln_proj_kernel<<<65536 / 8, 256, K1_SMEM>>>(x, nw, nb, Wa, Wb);
    opm_kernel<<<dim3(64, 128), 512, SMEM2>>>(bo, out);
}